// round 8
// baseline (speedup 1.0000x reference)
#include <cuda_runtime.h>

// Problem constants
#define DIMC 192
#define RR   48            // DIM/RED
#define BB   4
#define HH   256
#define WW   256
#define PLANE (HH*WW)      // 65536
#define NPLANES (BB*DIMC)  // 768
#define EPS_BN 1e-5f

// Scratch (no allocations allowed)
__device__ float g_partial[NPLANES * 4];   // per-quarter-plane sums
__device__ float g_wt[NPLANES * 4];        // 4 surviving masked taps per plane

// ---------------------------------------------------------------------------
// Kernel 1: partial sums for channel-wise mean. 3072 blocks x 256 threads.
// Each block reduces one quarter (16384 floats) of one plane.
// 4 independent accumulators -> deep load pipelining. Measured 32.6us @6.3TB/s.
// ---------------------------------------------------------------------------
__global__ void __launch_bounds__(256)
pool_partial_kernel(const float* __restrict__ x) {
    int bid = blockIdx.x;                  // [0, 3072)
    int plane = bid >> 2;
    int quarter = bid & 3;
    const float4* p = reinterpret_cast<const float4*>(
        x + (size_t)plane * PLANE + quarter * (PLANE / 4));
    float s0 = 0.f, s1 = 0.f, s2 = 0.f, s3 = 0.f;
    #pragma unroll
    for (int j = 0; j < 4; ++j) {
        float4 v0 = p[threadIdx.x + (4*j+0) * 256];
        float4 v1 = p[threadIdx.x + (4*j+1) * 256];
        float4 v2 = p[threadIdx.x + (4*j+2) * 256];
        float4 v3 = p[threadIdx.x + (4*j+3) * 256];
        s0 += (v0.x + v0.y) + (v0.z + v0.w);
        s1 += (v1.x + v1.y) + (v1.z + v1.w);
        s2 += (v2.x + v2.y) + (v2.z + v2.w);
        s3 += (v3.x + v3.y) + (v3.z + v3.w);
    }
    float s = (s0 + s1) + (s2 + s3);
    #pragma unroll
    for (int o = 16; o > 0; o >>= 1) s += __shfl_down_sync(0xffffffffu, s, o);
    __shared__ float sm[8];
    int lane = threadIdx.x & 31, w = threadIdx.x >> 5;
    if (lane == 0) sm[w] = s;
    __syncthreads();
    if (threadIdx.x < 8) {
        float v = sm[threadIdx.x];
        #pragma unroll
        for (int o = 4; o > 0; o >>= 1) v += __shfl_down_sync(0xffu, v, o);
        if (threadIdx.x == 0) g_partial[bid] = v;
    }
}

// ---------------------------------------------------------------------------
// Kernel 2 (fused): per-block redundant t = relu(BN(pooled @ w1^T)), then
// warp-per-weight dot products for the 4 surviving masked taps.
// grid = 192 blocks x 256 threads; each block produces 16 weights.
// ---------------------------------------------------------------------------
__global__ void __launch_bounds__(256)
fused_wt_kernel(const float* __restrict__ w1,
                const float* __restrict__ gamma,
                const float* __restrict__ beta,
                const float* __restrict__ rmean,
                const float* __restrict__ rvar,
                const float* __restrict__ w2,
                const float* __restrict__ b2) {
    __shared__ float sp[NPLANES];     // pooled means
    __shared__ float st[BB * RR];     // hidden t
    for (int j = threadIdx.x; j < NPLANES; j += 256) {
        sp[j] = (g_partial[4*j] + g_partial[4*j+1] + g_partial[4*j+2] + g_partial[4*j+3])
                * (1.f / (float)PLANE);
    }
    __syncthreads();
    if (threadIdx.x < BB * RR) {
        int b = threadIdx.x / RR;
        int r = threadIdx.x % RR;
        const float* pb = &sp[b * DIMC];
        const float* wr = &w1[r * DIMC];
        float acc = 0.f;
        #pragma unroll 4
        for (int k = 0; k < DIMC; ++k) acc = fmaf(pb[k], wr[k], acc);
        acc = gamma[r] * (acc - rmean[r]) * rsqrtf(rvar[r] + EPS_BN) + beta[r];
        st[threadIdx.x] = fmaxf(acc, 0.f);
    }
    __syncthreads();

    int lane = threadIdx.x & 31;
    int warp = threadIdx.x >> 5;      // 0..7
    #pragma unroll
    for (int i = 0; i < 2; ++i) {
        int idx = blockIdx.x * 16 + warp * 2 + i;   // [0, 3072)
        int b   = idx / (DIMC * 4);
        int rem = idx % (DIMC * 4);
        int c   = rem >> 2;
        int k   = rem & 3;
        int row = c * 9 + k;                        // w2 row (K*K=9 taps)
        const float* wr = &w2[(size_t)row * RR];
        const float* tb = &st[b * RR];
        float acc = tb[lane] * wr[lane];
        if (lane < 16) acc = fmaf(tb[lane + 32], wr[lane + 32], acc);
        #pragma unroll
        for (int o = 16; o > 0; o >>= 1) acc += __shfl_down_sync(0xffffffffu, acc, o);
        if (lane == 0) g_wt[idx] = acc + b2[row];
    }
}

// ---------------------------------------------------------------------------
// Kernel 3: masked depthwise conv (4 taps) + bias. R4-proven body (68.3us at
// 6.6TB/s with 4-row blocks), now 8-row blocks (512 threads) to cut the
// above-row halo from 25% to 12.5% of input traffic.
// out[y][x] = w0*X[y-1][x-1] + w1*X[y-1][x] + w2*X[y-1][x+1] + w3*X[y][x-1] + b
// grid: 768 planes * 32 row-groups; block 512 = 64 x-threads x 8 rows,
// each thread produces a float4 (4 consecutive x).
// ---------------------------------------------------------------------------
__global__ void __launch_bounds__(512, 4)
conv_kernel(const float* __restrict__ x,
            const float* __restrict__ bias,
            float* __restrict__ out) {
    int plane = blockIdx.x >> 5;
    int rg    = blockIdx.x & 31;
    int ty = threadIdx.x >> 6;         // 0..7
    int tx = threadIdx.x & 63;
    int y  = rg * 8 + ty;
    int x0 = tx << 2;

    const float* Xp  = x + (size_t)plane * PLANE;
    const float* cur = Xp + y * WW;

    float4 c4 = *reinterpret_cast<const float4*>(cur + x0);
    float cl  = (x0 > 0) ? cur[x0 - 1] : 0.f;

    float4 a4 = make_float4(0.f, 0.f, 0.f, 0.f);
    float al = 0.f, ar = 0.f;
    if (y > 0) {
        const float* ab = cur - WW;
        a4 = *reinterpret_cast<const float4*>(ab + x0);
        al = (x0 > 0)    ? ab[x0 - 1] : 0.f;
        ar = (x0 < WW-4) ? ab[x0 + 4] : 0.f;
    }

    const float4 w = *reinterpret_cast<const float4*>(g_wt + plane * 4);
    float bv = __ldg(&bias[plane % DIMC]);

    float4 o;
    o.x = fmaf(w.x, al,   fmaf(w.y, a4.x, fmaf(w.z, a4.y, fmaf(w.w, cl,   bv))));
    o.y = fmaf(w.x, a4.x, fmaf(w.y, a4.y, fmaf(w.z, a4.z, fmaf(w.w, c4.x, bv))));
    o.z = fmaf(w.x, a4.y, fmaf(w.y, a4.z, fmaf(w.z, a4.w, fmaf(w.w, c4.y, bv))));
    o.w = fmaf(w.x, a4.z, fmaf(w.y, a4.w, fmaf(w.z, ar,   fmaf(w.w, c4.z, bv))));

    *reinterpret_cast<float4*>(out + (size_t)plane * PLANE + y * WW + x0) = o;
}

// ---------------------------------------------------------------------------
extern "C" void kernel_launch(void* const* d_in, const int* in_sizes, int n_in,
                              void* d_out, int out_size) {
    const float* x     = (const float*)d_in[0];
    const float* w1    = (const float*)d_in[1];
    const float* gamma = (const float*)d_in[2];
    const float* beta  = (const float*)d_in[3];
    const float* rmean = (const float*)d_in[4];
    const float* rvar  = (const float*)d_in[5];
    const float* w2    = (const float*)d_in[6];
    const float* b2    = (const float*)d_in[7];
    const float* bias  = (const float*)d_in[8];
    float* out = (float*)d_out;

    pool_partial_kernel<<<NPLANES * 4, 256>>>(x);
    fused_wt_kernel<<<192, 256>>>(w1, gamma, beta, rmean, rvar, w2, b2);
    conv_kernel<<<NPLANES * 32, 512>>>(x, bias, out);
}

// round 9
// speedup vs baseline: 1.0588x; 1.0588x over previous
#include <cuda_runtime.h>

// Problem constants
#define DIMC 192
#define RR   48            // DIM/RED
#define BB   4
#define HH   256
#define WW   256
#define PLANE (HH*WW)      // 65536
#define NPLANES (BB*DIMC)  // 768
#define EPS_BN 1e-5f

// Scratch (no allocations allowed)
__device__ float g_partial[NPLANES * 4];   // per-quarter-plane sums
__device__ float g_wt[NPLANES * 4];        // 4 surviving masked taps per plane

// ---------------------------------------------------------------------------
// Kernel 1: partial sums for channel-wise mean. 3072 blocks x 256 threads.
// Each block reduces one quarter (16384 floats) of one plane.
// Measured: 32.4us @ 6.3TB/s (achieved ceiling). DO NOT TOUCH.
// ---------------------------------------------------------------------------
__global__ void __launch_bounds__(256)
pool_partial_kernel(const float* __restrict__ x) {
    int bid = blockIdx.x;                  // [0, 3072)
    int plane = bid >> 2;
    int quarter = bid & 3;
    const float4* p = reinterpret_cast<const float4*>(
        x + (size_t)plane * PLANE + quarter * (PLANE / 4));
    float s0 = 0.f, s1 = 0.f, s2 = 0.f, s3 = 0.f;
    #pragma unroll
    for (int j = 0; j < 4; ++j) {
        float4 v0 = p[threadIdx.x + (4*j+0) * 256];
        float4 v1 = p[threadIdx.x + (4*j+1) * 256];
        float4 v2 = p[threadIdx.x + (4*j+2) * 256];
        float4 v3 = p[threadIdx.x + (4*j+3) * 256];
        s0 += (v0.x + v0.y) + (v0.z + v0.w);
        s1 += (v1.x + v1.y) + (v1.z + v1.w);
        s2 += (v2.x + v2.y) + (v2.z + v2.w);
        s3 += (v3.x + v3.y) + (v3.z + v3.w);
    }
    float s = (s0 + s1) + (s2 + s3);
    #pragma unroll
    for (int o = 16; o > 0; o >>= 1) s += __shfl_down_sync(0xffffffffu, s, o);
    __shared__ float sm[8];
    int lane = threadIdx.x & 31, w = threadIdx.x >> 5;
    if (lane == 0) sm[w] = s;
    __syncthreads();
    if (threadIdx.x < 8) {
        float v = sm[threadIdx.x];
        #pragma unroll
        for (int o = 4; o > 0; o >>= 1) v += __shfl_down_sync(0xffu, v, o);
        if (threadIdx.x == 0) g_partial[bid] = v;
    }
}

// ---------------------------------------------------------------------------
// Kernel 2 (fused): per-block redundant t = relu(BN(pooled @ w1^T)), then
// warp-per-weight dot products for the 4 surviving masked taps.
// grid = 192 blocks x 256 threads; each block produces 16 weights.
// ---------------------------------------------------------------------------
__global__ void __launch_bounds__(256)
fused_wt_kernel(const float* __restrict__ w1,
                const float* __restrict__ gamma,
                const float* __restrict__ beta,
                const float* __restrict__ rmean,
                const float* __restrict__ rvar,
                const float* __restrict__ w2,
                const float* __restrict__ b2) {
    __shared__ float sp[NPLANES];     // pooled means
    __shared__ float st[BB * RR];     // hidden t
    for (int j = threadIdx.x; j < NPLANES; j += 256) {
        sp[j] = (g_partial[4*j] + g_partial[4*j+1] + g_partial[4*j+2] + g_partial[4*j+3])
                * (1.f / (float)PLANE);
    }
    __syncthreads();
    if (threadIdx.x < BB * RR) {
        int b = threadIdx.x / RR;
        int r = threadIdx.x % RR;
        const float* pb = &sp[b * DIMC];
        const float* wr = &w1[r * DIMC];
        float acc = 0.f;
        #pragma unroll 4
        for (int k = 0; k < DIMC; ++k) acc = fmaf(pb[k], wr[k], acc);
        acc = gamma[r] * (acc - rmean[r]) * rsqrtf(rvar[r] + EPS_BN) + beta[r];
        st[threadIdx.x] = fmaxf(acc, 0.f);
    }
    __syncthreads();

    int lane = threadIdx.x & 31;
    int warp = threadIdx.x >> 5;      // 0..7
    #pragma unroll
    for (int i = 0; i < 2; ++i) {
        int idx = blockIdx.x * 16 + warp * 2 + i;   // [0, 3072)
        int b   = idx / (DIMC * 4);
        int rem = idx % (DIMC * 4);
        int c   = rem >> 2;
        int k   = rem & 3;
        int row = c * 9 + k;                        // w2 row (K*K=9 taps)
        const float* wr = &w2[(size_t)row * RR];
        const float* tb = &st[b * RR];
        float acc = tb[lane] * wr[lane];
        if (lane < 16) acc = fmaf(tb[lane + 32], wr[lane + 32], acc);
        #pragma unroll
        for (int o = 16; o > 0; o >>= 1) acc += __shfl_down_sync(0xffffffffu, acc, o);
        if (lane == 0) g_wt[idx] = acc + b2[row];
    }
}

// ---------------------------------------------------------------------------
// Kernel 3: masked depthwise conv (4 taps) + bias. EXACT R4 body (measured
// 68.3us @ 6.6TB/s effective) with two byte-level tweaks:
//   (a) plane order REVERSED so conv's first waves read the x planes that
//       pool read last (still resident in the 126MB L2),
//   (b) __stcs output stores (evict-first) so the 201MB of write allocations
//       don't evict not-yet-read x lines from L2.
// out[y][x] = w0*X[y-1][x-1] + w1*X[y-1][x] + w2*X[y-1][x+1] + w3*X[y][x-1] + b
// grid: 768 planes * 64 row-groups; block 256 = 64 x-threads x 4 rows,
// each thread produces a float4 (4 consecutive x).
// ---------------------------------------------------------------------------
__global__ void __launch_bounds__(256, 8)
conv_kernel(const float* __restrict__ x,
            const float* __restrict__ bias,
            float* __restrict__ out) {
    int plane = (NPLANES - 1) - (blockIdx.x >> 6);
    int rg    = blockIdx.x & 63;
    int ty = threadIdx.x >> 6;
    int tx = threadIdx.x & 63;
    int y  = rg * 4 + ty;
    int x0 = tx << 2;

    const float* Xp  = x + (size_t)plane * PLANE;
    const float* cur = Xp + y * WW;

    float4 c4 = *reinterpret_cast<const float4*>(cur + x0);
    float cl  = (x0 > 0) ? cur[x0 - 1] : 0.f;

    float4 a4 = make_float4(0.f, 0.f, 0.f, 0.f);
    float al = 0.f, ar = 0.f;
    if (y > 0) {
        const float* ab = cur - WW;
        a4 = *reinterpret_cast<const float4*>(ab + x0);
        al = (x0 > 0)    ? ab[x0 - 1] : 0.f;
        ar = (x0 < WW-4) ? ab[x0 + 4] : 0.f;
    }

    const float4 w = *reinterpret_cast<const float4*>(g_wt + plane * 4);
    float bv = __ldg(&bias[plane % DIMC]);

    float4 o;
    o.x = fmaf(w.x, al,   fmaf(w.y, a4.x, fmaf(w.z, a4.y, fmaf(w.w, cl,   bv))));
    o.y = fmaf(w.x, a4.x, fmaf(w.y, a4.y, fmaf(w.z, a4.z, fmaf(w.w, c4.x, bv))));
    o.z = fmaf(w.x, a4.y, fmaf(w.y, a4.z, fmaf(w.z, a4.w, fmaf(w.w, c4.y, bv))));
    o.w = fmaf(w.x, a4.z, fmaf(w.y, a4.w, fmaf(w.z, ar,   fmaf(w.w, c4.z, bv))));

    __stcs(reinterpret_cast<float4*>(out + (size_t)plane * PLANE + y * WW + x0), o);
}

// ---------------------------------------------------------------------------
extern "C" void kernel_launch(void* const* d_in, const int* in_sizes, int n_in,
                              void* d_out, int out_size) {
    const float* x     = (const float*)d_in[0];
    const float* w1    = (const float*)d_in[1];
    const float* gamma = (const float*)d_in[2];
    const float* beta  = (const float*)d_in[3];
    const float* rmean = (const float*)d_in[4];
    const float* rvar  = (const float*)d_in[5];
    const float* w2    = (const float*)d_in[6];
    const float* b2    = (const float*)d_in[7];
    const float* bias  = (const float*)d_in[8];
    float* out = (float*)d_out;

    pool_partial_kernel<<<NPLANES * 4, 256>>>(x);
    fused_wt_kernel<<<192, 256>>>(w1, gamma, beta, rmean, rvar, w2, b2);
    conv_kernel<<<NPLANES * 64, 256>>>(x, bias, out);
}

// round 10
// speedup vs baseline: 1.0896x; 1.0291x over previous
#include <cuda_runtime.h>

// Problem constants
#define DIMC 192
#define RR   48            // DIM/RED
#define BB   4
#define HH   256
#define WW   256
#define PLANE (HH*WW)      // 65536
#define NPLANES (BB*DIMC)  // 768
#define EPS_BN 1e-5f

// Scratch (no allocations allowed)
__device__ float g_partial[NPLANES * 4];   // per-quarter-plane sums
__device__ float g_t[BB * RR];             // post-BN-ReLU hidden
__device__ float g_wt[NPLANES * 4];        // 4 surviving masked taps per plane

// ---------------------------------------------------------------------------
// Kernel 1: partial sums for channel-wise mean. 3072 blocks x 256 threads.
// Measured: 32.3us @ 6.37TB/s (achieved ceiling). DO NOT TOUCH.
// ---------------------------------------------------------------------------
__global__ void __launch_bounds__(256)
pool_partial_kernel(const float* __restrict__ x) {
    int bid = blockIdx.x;                  // [0, 3072)
    int plane = bid >> 2;
    int quarter = bid & 3;
    const float4* p = reinterpret_cast<const float4*>(
        x + (size_t)plane * PLANE + quarter * (PLANE / 4));
    float s0 = 0.f, s1 = 0.f, s2 = 0.f, s3 = 0.f;
    #pragma unroll
    for (int j = 0; j < 4; ++j) {
        float4 v0 = p[threadIdx.x + (4*j+0) * 256];
        float4 v1 = p[threadIdx.x + (4*j+1) * 256];
        float4 v2 = p[threadIdx.x + (4*j+2) * 256];
        float4 v3 = p[threadIdx.x + (4*j+3) * 256];
        s0 += (v0.x + v0.y) + (v0.z + v0.w);
        s1 += (v1.x + v1.y) + (v1.z + v1.w);
        s2 += (v2.x + v2.y) + (v2.z + v2.w);
        s3 += (v3.x + v3.y) + (v3.z + v3.w);
    }
    float s = (s0 + s1) + (s2 + s3);
    #pragma unroll
    for (int o = 16; o > 0; o >>= 1) s += __shfl_down_sync(0xffffffffu, s, o);
    __shared__ float sm[8];
    int lane = threadIdx.x & 31, w = threadIdx.x >> 5;
    if (lane == 0) sm[w] = s;
    __syncthreads();
    if (threadIdx.x < 8) {
        float v = sm[threadIdx.x];
        #pragma unroll
        for (int o = 4; o > 0; o >>= 1) v += __shfl_down_sync(0xffu, v, o);
        if (threadIdx.x == 0) g_partial[bid] = v;
    }
}

// ---------------------------------------------------------------------------
// Kernel 2: t = relu(BN(pooled @ w1^T)). Single block, 256 threads. (R4 exact)
// ---------------------------------------------------------------------------
__global__ void compute_t_kernel(const float* __restrict__ w1,
                                 const float* __restrict__ gamma,
                                 const float* __restrict__ beta,
                                 const float* __restrict__ rmean,
                                 const float* __restrict__ rvar) {
    __shared__ float sp[NPLANES];
    for (int j = threadIdx.x; j < NPLANES; j += 256) {
        sp[j] = (g_partial[4*j] + g_partial[4*j+1] + g_partial[4*j+2] + g_partial[4*j+3])
                * (1.f / (float)PLANE);
    }
    __syncthreads();
    if (threadIdx.x < BB * RR) {
        int b = threadIdx.x / RR;
        int r = threadIdx.x % RR;
        const float* pb = &sp[b * DIMC];
        const float* wr = &w1[r * DIMC];
        float acc = 0.f;
        #pragma unroll 4
        for (int k = 0; k < DIMC; ++k) acc = fmaf(pb[k], wr[k], acc);
        acc = gamma[r] * (acc - rmean[r]) * rsqrtf(rvar[r] + EPS_BN) + beta[r];
        g_t[threadIdx.x] = fmaxf(acc, 0.f);
    }
}

// ---------------------------------------------------------------------------
// Kernel 3: masked dynamic weights (R4 exact). 12 blocks x 256 threads.
// ---------------------------------------------------------------------------
__global__ void compute_wt_kernel(const float* __restrict__ w2,
                                  const float* __restrict__ b2) {
    __shared__ float st[BB * RR];
    if (threadIdx.x < BB * RR) st[threadIdx.x] = g_t[threadIdx.x];
    __syncthreads();
    int idx = blockIdx.x * 256 + threadIdx.x;   // [0, 3072)
    int b = idx / (DIMC * 4);
    int rem = idx % (DIMC * 4);
    int c = rem >> 2;
    int k = rem & 3;
    int row = c * 9 + k;                         // w2 row index (K*K=9 taps)
    const float* wr = &w2[row * RR];
    const float* tb = &st[b * RR];
    float acc = b2[row];
    #pragma unroll
    for (int r = 0; r < RR; ++r) acc = fmaf(tb[r], wr[r], acc);
    g_wt[idx] = acc;
}

// ---------------------------------------------------------------------------
// Kernel 4: masked depthwise conv (4 taps) + bias. BYTE-IDENTICAL to R4
// (measured 68.3us @ ~6.5TB/s effective). Forward plane order, plain stores.
// out[y][x] = w0*X[y-1][x-1] + w1*X[y-1][x] + w2*X[y-1][x+1] + w3*X[y][x-1] + b
// grid: 768 planes * 64 row-groups; block 256 = 64 x-threads x 4 rows,
// each thread produces a float4 (4 consecutive x).
// ---------------------------------------------------------------------------
__global__ void __launch_bounds__(256, 8)
conv_kernel(const float* __restrict__ x,
            const float* __restrict__ bias,
            float* __restrict__ out) {
    int plane = blockIdx.x >> 6;
    int rg    = blockIdx.x & 63;
    int ty = threadIdx.x >> 6;
    int tx = threadIdx.x & 63;
    int y  = rg * 4 + ty;
    int x0 = tx << 2;

    const float* Xp  = x + (size_t)plane * PLANE;
    const float* cur = Xp + y * WW;

    float4 c4 = *reinterpret_cast<const float4*>(cur + x0);
    float cl  = (x0 > 0) ? cur[x0 - 1] : 0.f;

    float4 a4 = make_float4(0.f, 0.f, 0.f, 0.f);
    float al = 0.f, ar = 0.f;
    if (y > 0) {
        const float* ab = cur - WW;
        a4 = *reinterpret_cast<const float4*>(ab + x0);
        al = (x0 > 0)    ? ab[x0 - 1] : 0.f;
        ar = (x0 < WW-4) ? ab[x0 + 4] : 0.f;
    }

    const float4 w = *reinterpret_cast<const float4*>(g_wt + plane * 4);
    float bv = __ldg(&bias[plane % DIMC]);

    float4 o;
    o.x = fmaf(w.x, al,   fmaf(w.y, a4.x, fmaf(w.z, a4.y, fmaf(w.w, cl,   bv))));
    o.y = fmaf(w.x, a4.x, fmaf(w.y, a4.y, fmaf(w.z, a4.z, fmaf(w.w, c4.x, bv))));
    o.z = fmaf(w.x, a4.y, fmaf(w.y, a4.z, fmaf(w.z, a4.w, fmaf(w.w, c4.y, bv))));
    o.w = fmaf(w.x, a4.z, fmaf(w.y, a4.w, fmaf(w.z, ar,   fmaf(w.w, c4.z, bv))));

    *reinterpret_cast<float4*>(out + (size_t)plane * PLANE + y * WW + x0) = o;
}

// ---------------------------------------------------------------------------
extern "C" void kernel_launch(void* const* d_in, const int* in_sizes, int n_in,
                              void* d_out, int out_size) {
    const float* x     = (const float*)d_in[0];
    const float* w1    = (const float*)d_in[1];
    const float* gamma = (const float*)d_in[2];
    const float* beta  = (const float*)d_in[3];
    const float* rmean = (const float*)d_in[4];
    const float* rvar  = (const float*)d_in[5];
    const float* w2    = (const float*)d_in[6];
    const float* b2    = (const float*)d_in[7];
    const float* bias  = (const float*)d_in[8];
    float* out = (float*)d_out;

    pool_partial_kernel<<<NPLANES * 4, 256>>>(x);
    compute_t_kernel<<<1, 256>>>(w1, gamma, beta, rmean, rvar);
    compute_wt_kernel<<<12, 256>>>(w2, b2);
    conv_kernel<<<NPLANES * 64, 256>>>(x, bias, out);
}

// round 11
// speedup vs baseline: 1.3386x; 1.2285x over previous
#include <cuda_runtime.h>

// Problem constants
#define DIMC 192
#define RR   48            // DIM/RED
#define BB   4
#define HH   256
#define WW   256
#define PLANE (HH*WW)      // 65536
#define NPLANES (BB*DIMC)  // 768
#define EPS_BN 1e-5f

// Scratch (no allocations allowed)
__device__ float g_partial[NPLANES * 4];   // per-quarter-plane sums

// ---------------------------------------------------------------------------
// Kernel 1: partial sums for channel-wise mean. 3072 blocks x 256 threads.
// Measured: 32.3us @ 6.37TB/s (achieved ceiling). DO NOT TOUCH.
// ---------------------------------------------------------------------------
__global__ void __launch_bounds__(256)
pool_partial_kernel(const float* __restrict__ x) {
    int bid = blockIdx.x;                  // [0, 3072)
    int plane = bid >> 2;
    int quarter = bid & 3;
    const float4* p = reinterpret_cast<const float4*>(
        x + (size_t)plane * PLANE + quarter * (PLANE / 4));
    float s0 = 0.f, s1 = 0.f, s2 = 0.f, s3 = 0.f;
    #pragma unroll
    for (int j = 0; j < 4; ++j) {
        float4 v0 = p[threadIdx.x + (4*j+0) * 256];
        float4 v1 = p[threadIdx.x + (4*j+1) * 256];
        float4 v2 = p[threadIdx.x + (4*j+2) * 256];
        float4 v3 = p[threadIdx.x + (4*j+3) * 256];
        s0 += (v0.x + v0.y) + (v0.z + v0.w);
        s1 += (v1.x + v1.y) + (v1.z + v1.w);
        s2 += (v2.x + v2.y) + (v2.z + v2.w);
        s3 += (v3.x + v3.y) + (v3.z + v3.w);
    }
    float s = (s0 + s1) + (s2 + s3);
    #pragma unroll
    for (int o = 16; o > 0; o >>= 1) s += __shfl_down_sync(0xffffffffu, s, o);
    __shared__ float sm[8];
    int lane = threadIdx.x & 31, w = threadIdx.x >> 5;
    if (lane == 0) sm[w] = s;
    __syncthreads();
    if (threadIdx.x < 8) {
        float v = sm[threadIdx.x];
        #pragma unroll
        for (int o = 4; o > 0; o >>= 1) v += __shfl_down_sync(0xffu, v, o);
        if (threadIdx.x == 0) g_partial[bid] = v;
    }
}

// ---------------------------------------------------------------------------
// Kernel 2 (fused): one block per plane. Prologue computes this plane's 4
// masked taps from g_partial (t = relu(BN(pooled @ w1^T)), then 4 dots with
// w2 rows). Main loop = byte-identical R4 conv body over 64 row-groups.
// out[y][x] = w0*X[y-1][x-1] + w1*X[y-1][x] + w2*X[y-1][x+1] + w3*X[y][x-1]+b
// ---------------------------------------------------------------------------
__global__ void __launch_bounds__(256, 8)
fused_conv_kernel(const float* __restrict__ x,
                  const float* __restrict__ w1,
                  const float* __restrict__ gamma,
                  const float* __restrict__ beta,
                  const float* __restrict__ rmean,
                  const float* __restrict__ rvar,
                  const float* __restrict__ w2,
                  const float* __restrict__ b2,
                  const float* __restrict__ bias,
                  float* __restrict__ out) {
    int plane = blockIdx.x;            // [0, 768)
    int b = plane / DIMC;
    int c = plane % DIMC;
    int lane = threadIdx.x & 31;
    int warp = threadIdx.x >> 5;       // 0..7

    __shared__ float sp[DIMC];         // pooled means for batch b
    __shared__ float st[RR];           // hidden t for batch b
    __shared__ float sw[4];            // this plane's 4 taps

    // pooled means (768 contiguous partials for batch b -> 192 means)
    if (threadIdx.x < DIMC) {
        float4 v = *reinterpret_cast<const float4*>(
            g_partial + b * DIMC * 4 + threadIdx.x * 4);
        sp[threadIdx.x] = ((v.x + v.y) + (v.z + v.w)) * (1.f / (float)PLANE);
    }
    __syncthreads();

    // t[r] = relu(BN(sum_k sp[k] * w1[r,k])); warp w handles r = w*6 + i
    #pragma unroll
    for (int i = 0; i < RR / 8; ++i) {
        int r = warp * (RR / 8) + i;
        const float* wr = w1 + r * DIMC;
        float acc = 0.f;
        #pragma unroll
        for (int k = 0; k < DIMC / 32; ++k)
            acc = fmaf(sp[lane + 32 * k], wr[lane + 32 * k], acc);
        #pragma unroll
        for (int o = 16; o > 0; o >>= 1)
            acc += __shfl_down_sync(0xffffffffu, acc, o);
        if (lane == 0) {
            acc = gamma[r] * (acc - rmean[r]) * rsqrtf(rvar[r] + EPS_BN) + beta[r];
            st[r] = fmaxf(acc, 0.f);
        }
    }
    __syncthreads();

    // 4 surviving masked taps: warp k computes wt[c*9+k] = t . w2[row] + b2
    if (warp < 4) {
        int row = c * 9 + warp;
        const float* wr = w2 + (size_t)row * RR;
        float acc = st[lane] * wr[lane];
        if (lane < 16) acc = fmaf(st[lane + 32], wr[lane + 32], acc);
        #pragma unroll
        for (int o = 16; o > 0; o >>= 1)
            acc += __shfl_down_sync(0xffffffffu, acc, o);
        if (lane == 0) sw[warp] = acc + b2[row];
    }
    __syncthreads();

    const float w0 = sw[0], w1v = sw[1], w2v = sw[2], w3 = sw[3];
    const float bv = __ldg(&bias[c]);

    int ty = threadIdx.x >> 6;         // 0..3
    int tx = threadIdx.x & 63;
    int x0 = tx << 2;
    const float* Xp = x   + (size_t)plane * PLANE;
    float*       Op = out + (size_t)plane * PLANE;

    #pragma unroll 2
    for (int rg = 0; rg < 64; ++rg) {
        int y = rg * 4 + ty;
        const float* cur = Xp + y * WW;

        float4 c4 = *reinterpret_cast<const float4*>(cur + x0);
        float cl  = (x0 > 0) ? cur[x0 - 1] : 0.f;

        float4 a4 = make_float4(0.f, 0.f, 0.f, 0.f);
        float al = 0.f, ar = 0.f;
        if (y > 0) {
            const float* ab = cur - WW;
            a4 = *reinterpret_cast<const float4*>(ab + x0);
            al = (x0 > 0)      ? ab[x0 - 1] : 0.f;
            ar = (x0 < WW - 4) ? ab[x0 + 4] : 0.f;
        }

        float4 o;
        o.x = fmaf(w0, al,   fmaf(w1v, a4.x, fmaf(w2v, a4.y, fmaf(w3, cl,   bv))));
        o.y = fmaf(w0, a4.x, fmaf(w1v, a4.y, fmaf(w2v, a4.z, fmaf(w3, c4.x, bv))));
        o.z = fmaf(w0, a4.y, fmaf(w1v, a4.z, fmaf(w2v, a4.w, fmaf(w3, c4.y, bv))));
        o.w = fmaf(w0, a4.z, fmaf(w1v, a4.w, fmaf(w2v, ar,   fmaf(w3, c4.z, bv))));

        *reinterpret_cast<float4*>(Op + y * WW + x0) = o;
    }
}

// ---------------------------------------------------------------------------
extern "C" void kernel_launch(void* const* d_in, const int* in_sizes, int n_in,
                              void* d_out, int out_size) {
    const float* x     = (const float*)d_in[0];
    const float* w1    = (const float*)d_in[1];
    const float* gamma = (const float*)d_in[2];
    const float* beta  = (const float*)d_in[3];
    const float* rmean = (const float*)d_in[4];
    const float* rvar  = (const float*)d_in[5];
    const float* w2    = (const float*)d_in[6];
    const float* b2    = (const float*)d_in[7];
    const float* bias  = (const float*)d_in[8];
    float* out = (float*)d_out;

    pool_partial_kernel<<<NPLANES * 4, 256>>>(x);
    fused_conv_kernel<<<NPLANES, 256>>>(x, w1, gamma, beta, rmean, rvar,
                                        w2, b2, bias, out);
}